// round 13
// baseline (speedup 1.0000x reference)
#include <cuda_runtime.h>
#include <cuda_fp16.h>

// Problem constants
#define B   2
#define D   160
#define H   192
#define W   160
#define HW  (H * W)          // 30720
#define DHW (D * H * W)      // 4915200
#define NVOX (B * DHW)       // 9830400 per channel
#define CH  5
#define WIN 9
#define PAD 4
#define INV_N (1.0f / 729.0f)

// 4-half units (pass3)
#define W4    (W / 4)        // 40
#define HW4   (HW / 4)       // 7680
#define DHW4  (DHW / 4)      // 1228800
#define NVOX4 (NVOX / 4)     // 2457600

// float4 units (grad)
#define WQ   (W / 4)         // 40
#define HWQ  (HW / 4)        // 7680
#define DHWQ (DHW / 4)       // 1228800

// H segmentation for k_pass12 (one third per launch)
#define HSEG  64
#define NSEGH (H / HSEG)     // 3
#define NCHUNK 18            // (HSEG + 2*PAD) / 4 rows per chunk

// pass3: per-launch h-range = H/NSEGH rows = 16 hq groups
#define HQ_PER_T ((H / 4) / NSEGH)   // 16

// D segmentation for k_pass3
#define SEG3  8
#define DSEG3 (D / SEG3)     // 20

// D segmentation for k_grad
#define GSEGD 4
#define GDSEG (D / GSEGD)    // 40

// Scratch — fp16 box-sums, uint2-typed for 8B alignment
__device__ uint2 g_bufH4[CH * NVOX4];
__device__ double g_acc[4];           // cc_sum, dx_sum, dy_sum, dz_sum

__device__ __forceinline__ void warp_reduce_atomic(float v, double* dst) {
#pragma unroll
    for (int off = 16; off > 0; off >>= 1)
        v += __shfl_down_sync(0xFFFFFFFFu, v, off);
    if ((threadIdx.x & 31) == 0) atomicAdd(dst, (double)v);
}

__device__ __forceinline__ float4 h4_to_f4(uint2 u) {
    const __half2 a = *reinterpret_cast<const __half2*>(&u.x);
    const __half2 b = *reinterpret_cast<const __half2*>(&u.y);
    const float2 fa = __half22float2(a);
    const float2 fb = __half22float2(b);
    return make_float4(fa.x, fa.y, fb.x, fb.y);
}

__global__ void k_zero() {
    if (threadIdx.x < 4) g_acc[threadIdx.x] = 0.0;
}

// ---------------------------------------------------------------------------
// Fused pass 1+2, software-pipelined (R11 structure). One h-third per launch.
__global__ void k_pass12(const float* __restrict__ F, const float* __restrict__ M,
                         int hs) {
    __shared__ float stg[2][4][2][W + 2 * PAD];  // [buf][row][f/m][w]
    __shared__ float ring[WIN][CH][W];

    __half2* __restrict__ bufH2 = (__half2*)g_bufH4;

    const int w = threadIdx.x;
    int blk = blockIdx.x;                        // over B*D = 320
    const int d  = blk % D;
    const int b  = blk / D;
    const int h0 = hs * HSEG;

    const size_t plane = (size_t)(b * D + d) * HW;
    const float* __restrict__ Fp = F + plane;
    const float* __restrict__ Mp = M + plane;
    const bool even = ((w & 1) == 0);

#pragma unroll
    for (int sl = 0; sl < WIN; sl++)
#pragma unroll
        for (int c = 0; c < CH; c++) ring[sl][c][w] = 0.f;
    if (w < PAD) {
#pragma unroll
        for (int bu = 0; bu < 2; bu++)
#pragma unroll
            for (int r = 0; r < 4; r++)
#pragma unroll
                for (int c = 0; c < 2; c++) {
                    stg[bu][r][c][w] = 0.f;
                    stg[bu][r][c][w + W + PAD] = 0.f;
                }
    }

    float rf[4], rm[4];

#define LDGCHUNK(jj)                                                         \
    {                                                                        \
        _Pragma("unroll")                                                    \
        for (int i = 0; i < 4; i++) {                                        \
            const int r_ = h0 - 4 + 4 * (jj) + i;                            \
            const bool v_ = (r_ >= 0 && r_ < H);                             \
            rf[i] = v_ ? Fp[r_ * W + w] : 0.f;                               \
            rm[i] = v_ ? Mp[r_ * W + w] : 0.f;                               \
        }                                                                    \
    }

#define STSCHUNK(bu)                                                         \
    {                                                                        \
        _Pragma("unroll")                                                    \
        for (int i = 0; i < 4; i++) {                                        \
            stg[bu][i][0][w + PAD] = rf[i];                                  \
            stg[bu][i][1][w + PAD] = rm[i];                                  \
        }                                                                    \
    }

    float s0 = 0.f, s1 = 0.f, s2 = 0.f, s3 = 0.f, s4 = 0.f;
    int slot = 0;

#define PROC(bu, i)                                                          \
    {                                                                        \
        float n0 = 0.f, n1 = 0.f, n2 = 0.f, n3 = 0.f, n4 = 0.f;              \
        _Pragma("unroll")                                                    \
        for (int k = 0; k < WIN; k++) {                                      \
            const float fk = stg[bu][i][0][w + k];                           \
            const float mk = stg[bu][i][1][w + k];                           \
            n0 += fk; n1 += mk;                                              \
            n2 = fmaf(fk, fk, n2);                                           \
            n3 = fmaf(mk, mk, n3);                                           \
            n4 = fmaf(fk, mk, n4);                                           \
        }                                                                    \
        s0 += n0 - ring[slot][0][w]; ring[slot][0][w] = n0;                  \
        s1 += n1 - ring[slot][1][w]; ring[slot][1][w] = n1;                  \
        s2 += n2 - ring[slot][2][w]; ring[slot][2][w] = n2;                  \
        s3 += n3 - ring[slot][3][w]; ring[slot][3][w] = n3;                  \
        s4 += n4 - ring[slot][4][w]; ring[slot][4][w] = n4;                  \
        slot = (slot == WIN - 1) ? 0 : slot + 1;                             \
    }

#define EMIT(h_)                                                             \
    {                                                                        \
        const float t0 = __shfl_down_sync(0xFFFFFFFFu, s0, 1);               \
        const float t1 = __shfl_down_sync(0xFFFFFFFFu, s1, 1);               \
        const float t2 = __shfl_down_sync(0xFFFFFFFFu, s2, 1);               \
        const float t3 = __shfl_down_sync(0xFFFFFFFFu, s3, 1);               \
        const float t4 = __shfl_down_sync(0xFFFFFFFFu, s4, 1);               \
        if (even) {                                                          \
            const size_t o2 = (plane + (size_t)(h_) * W + w) >> 1;           \
            bufH2[((size_t)0 * NVOX >> 1) + o2] = __floats2half2_rn(s0, t0); \
            bufH2[((size_t)1 * NVOX >> 1) + o2] = __floats2half2_rn(s1, t1); \
            bufH2[((size_t)2 * NVOX >> 1) + o2] = __floats2half2_rn(s2, t2); \
            bufH2[((size_t)3 * NVOX >> 1) + o2] = __floats2half2_rn(s3, t3); \
            bufH2[((size_t)4 * NVOX >> 1) + o2] = __floats2half2_rn(s4, t4); \
        }                                                                    \
    }

    LDGCHUNK(0);
    STSCHUNK(0);
    __syncthreads();

#pragma unroll 1
    for (int j = 0; j < NCHUNK; j++) {
        if (j < NCHUNK - 1) LDGCHUNK(j + 1);

        const int bu = j & 1;
        if (j >= 2) {
            const int hb = h0 + 4 * (j - 2);
            PROC(bu, 0) EMIT(hb + 0);
            PROC(bu, 1) EMIT(hb + 1);
            PROC(bu, 2) EMIT(hb + 2);
            PROC(bu, 3) EMIT(hb + 3);
        } else {
            PROC(bu, 0) PROC(bu, 1) PROC(bu, 2) PROC(bu, 3)
        }

        if (j < NCHUNK - 1) {
            STSCHUNK(bu ^ 1);
            __syncthreads();
        }
    }
#undef LDGCHUNK
#undef STSCHUNK
#undef PROC
#undef EMIT
}

// ---------------------------------------------------------------------------
// Pass 3: two-pointer D running window. One h-third per launch (hq offset).
__global__ void __launch_bounds__(160) k_pass3_cc(int hq0) {
    const int t = threadIdx.x;
    const int qw = t % W4;
    const int hs = t / W4;                   // 0..3
    int blk = blockIdx.x;                    // over B * HQ_PER_T * SEG3 = 256
    const int seg = blk % SEG3; blk /= SEG3;
    const int hq = hq0 + blk % HQ_PER_T;
    const int b  = blk / HQ_PER_T;
    const int h  = hq * 4 + hs;
    const int d0 = seg * DSEG3;

    const size_t col = (size_t)b * DHW4 + (size_t)h * W4 + qw;

    float4 s[CH];
#pragma unroll
    for (int c = 0; c < CH; c++) s[c] = make_float4(0.f, 0.f, 0.f, 0.f);

#pragma unroll 1
    for (int i = 0; i < WIN; i++) {
        const int d = d0 - PAD + i;
        if (d >= 0) {
#pragma unroll
            for (int c = 0; c < CH; c++) {
                const float4 f = h4_to_f4(g_bufH4[(size_t)c * NVOX4 + col + (size_t)d * HW4]);
                s[c].x += f.x; s[c].y += f.y; s[c].z += f.z; s[c].w += f.w;
            }
        }
    }

    float local = 0.f;
#pragma unroll 2
    for (int u = 0; u < DSEG3; u++) {
        const int d = d0 + u;
#define CCC(comp)                                                            \
        {                                                                    \
            const float mf  = s[0].comp * INV_N;                             \
            const float mm  = s[1].comp * INV_N;                             \
            const float vF  = s[2].comp - mf * mf;                           \
            const float vM  = s[3].comp - mm * mm;                           \
            const float cov = s[4].comp - mf * mm;                           \
            local += (cov * cov) / (vF * vM + 1e-8f);                        \
        }
        CCC(x) CCC(y) CCC(z) CCC(w)
#undef CCC

        const int dn = d + PAD + 1;
        const int dm = d - PAD;
        if (dn < D) {
#pragma unroll
            for (int c = 0; c < CH; c++) {
                const float4 f = h4_to_f4(g_bufH4[(size_t)c * NVOX4 + col + (size_t)dn * HW4]);
                s[c].x += f.x; s[c].y += f.y; s[c].z += f.z; s[c].w += f.w;
            }
        }
        if (dm >= 0) {
#pragma unroll
            for (int c = 0; c < CH; c++) {
                const float4 f = h4_to_f4(g_bufH4[(size_t)c * NVOX4 + col + (size_t)dm * HW4]);
                s[c].x -= f.x; s[c].y -= f.y; s[c].z -= f.z; s[c].w -= f.w;
            }
        }
    }

    warp_reduce_atomic(local, &g_acc[0]);
}

// ---------------------------------------------------------------------------
// Flow gradient: d-walk with register reuse (side stream).
__global__ void k_grad(const float* __restrict__ flow) {
    const float4* __restrict__ f4 = (const float4*)flow;
    const int t = threadIdx.x;
    const int qw = t % WQ;
    const int hs = t / WQ;                   // 0..3
    int blk = blockIdx.x;                    // over B*3 * (H/4) * GSEGD = 1152
    const int seg = blk % GSEGD; blk /= GSEGD;
    const int hq = blk % (H / 4);
    const int bc = blk / (H / 4);            // 0..5 (b*3 + c)
    const int h  = hq * 4 + hs;
    const int d0 = seg * GDSEG;

    const bool hasH = (h < H - 1);
    const bool hasW = (qw < WQ - 1);

    size_t base = (size_t)bc * DHWQ + (size_t)d0 * HWQ + (size_t)h * WQ + qw;
    float sdx = 0.f, sdy = 0.f, sdz = 0.f;
    float4 v = f4[base];

    const int dend = d0 + GDSEG;
#pragma unroll 4
    for (int d = d0; d < dend; d++) {
        sdz += fabsf(v.y - v.x) + fabsf(v.z - v.y) + fabsf(v.w - v.z);
        if (hasW) sdz += fabsf(flow[4 * base + 4] - v.w);
        if (hasH) {
            const float4 hn = f4[base + WQ];
            sdx += fabsf(hn.x - v.x) + fabsf(hn.y - v.y)
                 + fabsf(hn.z - v.z) + fabsf(hn.w - v.w);
        }
        if (d < D - 1) {
            const float4 dn = f4[base + HWQ];
            sdy += fabsf(dn.x - v.x) + fabsf(dn.y - v.y)
                 + fabsf(dn.z - v.z) + fabsf(dn.w - v.w);
            v = dn;
        }
        base += HWQ;
    }

    warp_reduce_atomic(sdx, &g_acc[1]);
    warp_reduce_atomic(sdy, &g_acc[2]);
    warp_reduce_atomic(sdz, &g_acc[3]);
}

// ---------------------------------------------------------------------------
__global__ void k_finalize(float* __restrict__ out) {
    const double L_sim = -(g_acc[0] / (double)NVOX);
    const double ndx = (double)B * 3.0 * D * (H - 1) * W;
    const double ndy = (double)B * 3.0 * (D - 1) * H * W;
    const double ndz = (double)B * 3.0 * D * H * (W - 1);
    const double L_reg = g_acc[1] / ndx + g_acc[2] / ndy + g_acc[3] / ndz;
    out[0] = (float)(L_sim + L_reg);
    out[1] = (float)L_sim;
    out[2] = (float)L_reg;
}

// ---------------------------------------------------------------------------
extern "C" void kernel_launch(void* const* d_in, const int* in_sizes, int n_in,
                              void* d_out, int out_size) {
    const float* I_fixed = (const float*)d_in[0];
    const float* I_moved = (const float*)d_in[1];
    const float* flow    = (const float*)d_in[2];
    float* out = (float*)d_out;

    static cudaStream_t s_grad = 0, s_p3 = 0;
    static cudaEvent_t ev_fork = 0, ev_grad = 0, ev_p3 = 0;
    static cudaEvent_t ev_t[NSEGH] = {0, 0, 0};
    if (s_grad == 0) {
        cudaStreamCreateWithFlags(&s_grad, cudaStreamNonBlocking);
        cudaStreamCreateWithFlags(&s_p3, cudaStreamNonBlocking);
        cudaEventCreateWithFlags(&ev_fork, cudaEventDisableTiming);
        cudaEventCreateWithFlags(&ev_grad, cudaEventDisableTiming);
        cudaEventCreateWithFlags(&ev_p3, cudaEventDisableTiming);
        for (int t = 0; t < NSEGH; t++)
            cudaEventCreateWithFlags(&ev_t[t], cudaEventDisableTiming);
    }

    k_zero<<<1, 32>>>();
    cudaEventRecord(ev_fork, 0);

    // grad fork (independent of everything except k_zero)
    cudaStreamWaitEvent(s_grad, ev_fork, 0);
    k_grad<<<B * 3 * (H / 4) * GSEGD, 160, 0, s_grad>>>(flow);
    cudaEventRecord(ev_grad, s_grad);

    // pass12 thirds on main stream; pass3 third t starts when third t's data is ready
    cudaStreamWaitEvent(s_p3, ev_fork, 0);
    for (int t = 0; t < NSEGH; t++) {
        k_pass12<<<B * D, W>>>(I_fixed, I_moved, t);
        cudaEventRecord(ev_t[t], 0);
        cudaStreamWaitEvent(s_p3, ev_t[t], 0);
        k_pass3_cc<<<B * HQ_PER_T * SEG3, 160, 0, s_p3>>>(t * HQ_PER_T);
    }
    cudaEventRecord(ev_p3, s_p3);

    cudaStreamWaitEvent(0, ev_p3, 0);
    cudaStreamWaitEvent(0, ev_grad, 0);
    k_finalize<<<1, 1>>>(out);
}

// round 14
// speedup vs baseline: 1.7245x; 1.7245x over previous
#include <cuda_runtime.h>
#include <cuda_fp16.h>

// Problem constants
#define B   2
#define D   160
#define H   192
#define W   160
#define HW  (H * W)          // 30720
#define DHW (D * H * W)      // 4915200
#define NVOX (B * DHW)       // 9830400 per channel
#define CH  5
#define WIN 9
#define PAD 4
#define INV_N (1.0f / 729.0f)

// 4-half units (pass3)
#define W4    (W / 4)        // 40
#define HW4   (HW / 4)       // 7680
#define DHW4  (DHW / 4)      // 1228800
#define NVOX4 (NVOX / 4)     // 2457600

// float4 units (grad)
#define WQ   (W / 4)         // 40
#define HWQ  (HW / 4)        // 7680
#define DHWQ (DHW / 4)       // 1228800

// H segmentation for k_pass12
#define HSEG  64
#define NSEGH (H / HSEG)     // 3
#define NCHUNK 18            // (HSEG + 2*PAD) / 4 rows per chunk

// D segmentation for k_pass3
#define SEG3  8
#define DSEG3 (D / SEG3)     // 20

// D segmentation for k_grad
#define GSEGD 4
#define GDSEG (D / GSEGD)    // 40

// Scratch — fp16 box-sums, uint2-typed for 8B alignment
__device__ uint2 g_bufH4[CH * NVOX4];
__device__ double g_acc[4] = {0.0, 0.0, 0.0, 0.0};  // self-resetting (finalize)

__device__ __forceinline__ void warp_reduce_atomic(float v, double* dst) {
#pragma unroll
    for (int off = 16; off > 0; off >>= 1)
        v += __shfl_down_sync(0xFFFFFFFFu, v, off);
    if ((threadIdx.x & 31) == 0) atomicAdd(dst, (double)v);
}

__device__ __forceinline__ float4 h4_to_f4(uint2 u) {
    const __half2 a = *reinterpret_cast<const __half2*>(&u.x);
    const __half2 b = *reinterpret_cast<const __half2*>(&u.y);
    const float2 fa = __half22float2(a);
    const float2 fb = __half22float2(b);
    return make_float4(fa.x, fa.y, fb.x, fb.y);
}

// ---------------------------------------------------------------------------
// Fused pass 1+2, software-pipelined, fp16 ring (halved ring smem + bytes).
// Window-exactness: the value ADDED to the running H-sum is the half-rounded
// value that will later be SUBTRACTED — no drift.
__global__ void __launch_bounds__(160, 6)
k_pass12(const float* __restrict__ F, const float* __restrict__ M) {
    __shared__ float2  stg[2][4][W + 2 * PAD];   // (f,m) pairs, 10.75KB
    __shared__ __half2 ring01[WIN][W];           // (sumF, sumM)   5.76KB
    __shared__ __half2 ring23[WIN][W];           // (sumF2, sumM2) 5.76KB
    __shared__ __half  ring4 [WIN][W];           // sumFM          2.88KB

    __half2* __restrict__ bufH2 = (__half2*)g_bufH4;

    const int w = threadIdx.x;
    int blk = blockIdx.x;                        // over B*D*NSEGH = 960
    const int hs = blk % NSEGH; blk /= NSEGH;
    const int d  = blk % D;
    const int b  = blk / D;
    const int h0 = hs * HSEG;

    const size_t plane = (size_t)(b * D + d) * HW;
    const float* __restrict__ Fp = F + plane;
    const float* __restrict__ Mp = M + plane;
    const bool even = ((w & 1) == 0);

    // Zero ring column (thread-private) and staging halos (once).
    const __half2 HZ = __floats2half2_rn(0.f, 0.f);
#pragma unroll
    for (int sl = 0; sl < WIN; sl++) {
        ring01[sl][w] = HZ;
        ring23[sl][w] = HZ;
        ring4 [sl][w] = __float2half_rn(0.f);
    }
    if (w < PAD) {
#pragma unroll
        for (int bu = 0; bu < 2; bu++)
#pragma unroll
            for (int r = 0; r < 4; r++) {
                stg[bu][r][w] = make_float2(0.f, 0.f);
                stg[bu][r][w + W + PAD] = make_float2(0.f, 0.f);
            }
    }

    float rf[4], rm[4];

#define LDGCHUNK(jj)                                                         \
    {                                                                        \
        _Pragma("unroll")                                                    \
        for (int i = 0; i < 4; i++) {                                        \
            const int r_ = h0 - 4 + 4 * (jj) + i;                            \
            const bool v_ = (r_ >= 0 && r_ < H);                             \
            rf[i] = v_ ? Fp[r_ * W + w] : 0.f;                               \
            rm[i] = v_ ? Mp[r_ * W + w] : 0.f;                               \
        }                                                                    \
    }

#define STSCHUNK(bu)                                                         \
    {                                                                        \
        _Pragma("unroll")                                                    \
        for (int i = 0; i < 4; i++)                                          \
            stg[bu][i][w + PAD] = make_float2(rf[i], rm[i]);                 \
    }

    float s0 = 0.f, s1 = 0.f, s2 = 0.f, s3 = 0.f, s4 = 0.f;
    int slot = 0;

    // PROC: 9-tap W box, round to fp16, update running sums + fp16 ring.
#define PROC(bu, i)                                                          \
    {                                                                        \
        float n0 = 0.f, n1 = 0.f, n2 = 0.f, n3 = 0.f, n4 = 0.f;              \
        _Pragma("unroll")                                                    \
        for (int k = 0; k < WIN; k++) {                                      \
            const float2 P = stg[bu][i][w + k];                              \
            n0 += P.x; n1 += P.y;                                            \
            n2 = fmaf(P.x, P.x, n2);                                         \
            n3 = fmaf(P.y, P.y, n3);                                         \
            n4 = fmaf(P.x, P.y, n4);                                         \
        }                                                                    \
        const __half2 h01 = __floats2half2_rn(n0, n1);                       \
        const __half2 h23 = __floats2half2_rn(n2, n3);                       \
        const __half  h4v = __float2half_rn(n4);                             \
        const float2 f01 = __half22float2(h01);                              \
        const float2 f23 = __half22float2(h23);                              \
        const float  f4  = __half2float(h4v);                                \
        const float2 g01 = __half22float2(ring01[slot][w]);                  \
        const float2 g23 = __half22float2(ring23[slot][w]);                  \
        const float  g4  = __half2float(ring4[slot][w]);                     \
        s0 += f01.x - g01.x; s1 += f01.y - g01.y;                            \
        s2 += f23.x - g23.x; s3 += f23.y - g23.y;                            \
        s4 += f4 - g4;                                                       \
        ring01[slot][w] = h01;                                               \
        ring23[slot][w] = h23;                                               \
        ring4 [slot][w] = h4v;                                               \
        slot = (slot == WIN - 1) ? 0 : slot + 1;                             \
    }

    // Even lanes store packed {own, lane+1} half2 per channel.
#define EMIT(h_)                                                             \
    {                                                                        \
        const float t0 = __shfl_down_sync(0xFFFFFFFFu, s0, 1);               \
        const float t1 = __shfl_down_sync(0xFFFFFFFFu, s1, 1);               \
        const float t2 = __shfl_down_sync(0xFFFFFFFFu, s2, 1);               \
        const float t3 = __shfl_down_sync(0xFFFFFFFFu, s3, 1);               \
        const float t4 = __shfl_down_sync(0xFFFFFFFFu, s4, 1);               \
        if (even) {                                                          \
            const size_t o2 = (plane + (size_t)(h_) * W + w) >> 1;           \
            bufH2[((size_t)0 * NVOX >> 1) + o2] = __floats2half2_rn(s0, t0); \
            bufH2[((size_t)1 * NVOX >> 1) + o2] = __floats2half2_rn(s1, t1); \
            bufH2[((size_t)2 * NVOX >> 1) + o2] = __floats2half2_rn(s2, t2); \
            bufH2[((size_t)3 * NVOX >> 1) + o2] = __floats2half2_rn(s3, t3); \
            bufH2[((size_t)4 * NVOX >> 1) + o2] = __floats2half2_rn(s4, t4); \
        }                                                                    \
    }

    LDGCHUNK(0);
    STSCHUNK(0);
    __syncthreads();

#pragma unroll 1
    for (int j = 0; j < NCHUNK; j++) {
        if (j < NCHUNK - 1) LDGCHUNK(j + 1);   // prefetch overlaps PROC

        const int bu = j & 1;
        if (j >= 2) {
            const int hb = h0 + 4 * (j - 2);
            PROC(bu, 0) EMIT(hb + 0);
            PROC(bu, 1) EMIT(hb + 1);
            PROC(bu, 2) EMIT(hb + 2);
            PROC(bu, 3) EMIT(hb + 3);
        } else {
            PROC(bu, 0) PROC(bu, 1) PROC(bu, 2) PROC(bu, 3)
        }

        if (j < NCHUNK - 1) {
            STSCHUNK(bu ^ 1);
            __syncthreads();
        }
    }
#undef LDGCHUNK
#undef STSCHUNK
#undef PROC
#undef EMIT
}

// ---------------------------------------------------------------------------
// Pass 3: two-pointer D running window (R12 best, single 768-block launch).
__global__ void __launch_bounds__(160) k_pass3_cc() {
    const int t = threadIdx.x;
    const int qw = t % W4;
    const int hs = t / W4;                   // 0..3
    int blk = blockIdx.x;                    // over B * (H/4) * SEG3 = 768
    const int seg = blk % SEG3; blk /= SEG3;
    const int hq = blk % (H / 4);
    const int b  = blk / (H / 4);
    const int h  = hq * 4 + hs;
    const int d0 = seg * DSEG3;

    const size_t col = (size_t)b * DHW4 + (size_t)h * W4 + qw;

    float4 s[CH];
#pragma unroll
    for (int c = 0; c < CH; c++) s[c] = make_float4(0.f, 0.f, 0.f, 0.f);

#pragma unroll 1
    for (int i = 0; i < WIN; i++) {
        const int d = d0 - PAD + i;
        if (d >= 0) {
#pragma unroll
            for (int c = 0; c < CH; c++) {
                const float4 f = h4_to_f4(g_bufH4[(size_t)c * NVOX4 + col + (size_t)d * HW4]);
                s[c].x += f.x; s[c].y += f.y; s[c].z += f.z; s[c].w += f.w;
            }
        }
    }

    float local = 0.f;
#pragma unroll 2
    for (int u = 0; u < DSEG3; u++) {
        const int d = d0 + u;
#define CCC(comp)                                                            \
        {                                                                    \
            const float mf  = s[0].comp * INV_N;                             \
            const float mm  = s[1].comp * INV_N;                             \
            const float vF  = s[2].comp - mf * mf;                           \
            const float vM  = s[3].comp - mm * mm;                           \
            const float cov = s[4].comp - mf * mm;                           \
            local += (cov * cov) / (vF * vM + 1e-8f);                        \
        }
        CCC(x) CCC(y) CCC(z) CCC(w)
#undef CCC

        const int dn = d + PAD + 1;
        const int dm = d - PAD;
        if (dn < D) {
#pragma unroll
            for (int c = 0; c < CH; c++) {
                const float4 f = h4_to_f4(g_bufH4[(size_t)c * NVOX4 + col + (size_t)dn * HW4]);
                s[c].x += f.x; s[c].y += f.y; s[c].z += f.z; s[c].w += f.w;
            }
        }
        if (dm >= 0) {
#pragma unroll
            for (int c = 0; c < CH; c++) {
                const float4 f = h4_to_f4(g_bufH4[(size_t)c * NVOX4 + col + (size_t)dm * HW4]);
                s[c].x -= f.x; s[c].y -= f.y; s[c].z -= f.z; s[c].w -= f.w;
            }
        }
    }

    warp_reduce_atomic(local, &g_acc[0]);
}

// ---------------------------------------------------------------------------
// Flow gradient: d-walk with register reuse (side stream).
__global__ void k_grad(const float* __restrict__ flow) {
    const float4* __restrict__ f4 = (const float4*)flow;
    const int t = threadIdx.x;
    const int qw = t % WQ;
    const int hs = t / WQ;                   // 0..3
    int blk = blockIdx.x;                    // over B*3 * (H/4) * GSEGD = 1152
    const int seg = blk % GSEGD; blk /= GSEGD;
    const int hq = blk % (H / 4);
    const int bc = blk / (H / 4);            // 0..5 (b*3 + c)
    const int h  = hq * 4 + hs;
    const int d0 = seg * GDSEG;

    const bool hasH = (h < H - 1);
    const bool hasW = (qw < WQ - 1);

    size_t base = (size_t)bc * DHWQ + (size_t)d0 * HWQ + (size_t)h * WQ + qw;
    float sdx = 0.f, sdy = 0.f, sdz = 0.f;
    float4 v = f4[base];

    const int dend = d0 + GDSEG;
#pragma unroll 4
    for (int d = d0; d < dend; d++) {
        sdz += fabsf(v.y - v.x) + fabsf(v.z - v.y) + fabsf(v.w - v.z);
        if (hasW) sdz += fabsf(flow[4 * base + 4] - v.w);
        if (hasH) {
            const float4 hn = f4[base + WQ];
            sdx += fabsf(hn.x - v.x) + fabsf(hn.y - v.y)
                 + fabsf(hn.z - v.z) + fabsf(hn.w - v.w);
        }
        if (d < D - 1) {
            const float4 dn = f4[base + HWQ];
            sdy += fabsf(dn.x - v.x) + fabsf(dn.y - v.y)
                 + fabsf(dn.z - v.z) + fabsf(dn.w - v.w);
            v = dn;
        }
        base += HWQ;
    }

    warp_reduce_atomic(sdx, &g_acc[1]);
    warp_reduce_atomic(sdy, &g_acc[2]);
    warp_reduce_atomic(sdz, &g_acc[3]);
}

// ---------------------------------------------------------------------------
// Finalize: emit outputs, then reset accumulators for the next replay
// (g_acc statically zero-initialized; every run ends reset -> deterministic).
__global__ void k_finalize(float* __restrict__ out) {
    const double L_sim = -(g_acc[0] / (double)NVOX);
    const double ndx = (double)B * 3.0 * D * (H - 1) * W;
    const double ndy = (double)B * 3.0 * (D - 1) * H * W;
    const double ndz = (double)B * 3.0 * D * H * (W - 1);
    const double L_reg = g_acc[1] / ndx + g_acc[2] / ndy + g_acc[3] / ndz;
    out[0] = (float)(L_sim + L_reg);
    out[1] = (float)L_sim;
    out[2] = (float)L_reg;
    g_acc[0] = 0.0; g_acc[1] = 0.0; g_acc[2] = 0.0; g_acc[3] = 0.0;
}

// ---------------------------------------------------------------------------
extern "C" void kernel_launch(void* const* d_in, const int* in_sizes, int n_in,
                              void* d_out, int out_size) {
    const float* I_fixed = (const float*)d_in[0];
    const float* I_moved = (const float*)d_in[1];
    const float* flow    = (const float*)d_in[2];
    float* out = (float*)d_out;

    static cudaStream_t s_side = 0;
    static cudaEvent_t ev_fork = 0, ev_join = 0;
    if (s_side == 0) {
        cudaStreamCreateWithFlags(&s_side, cudaStreamNonBlocking);
        cudaEventCreateWithFlags(&ev_fork, cudaEventDisableTiming);
        cudaEventCreateWithFlags(&ev_join, cudaEventDisableTiming);
    }

    // Fork: k_grad (reads flow only) runs concurrently with pass12/pass3.
    cudaEventRecord(ev_fork, 0);
    cudaStreamWaitEvent(s_side, ev_fork, 0);
    k_grad<<<B * 3 * (H / 4) * GSEGD, 160, 0, s_side>>>(flow);
    cudaEventRecord(ev_join, s_side);

    k_pass12<<<B * D * NSEGH, W>>>(I_fixed, I_moved);
    k_pass3_cc<<<B * (H / 4) * SEG3, 160>>>();

    cudaStreamWaitEvent(0, ev_join, 0);
    k_finalize<<<1, 1>>>(out);
}